// round 1
// baseline (speedup 1.0000x reference)
#include <cuda_runtime.h>
#include <math.h>

#define S_LEN   2048
#define DMODEL  1024
#define NHEADS  16
#define HDIM    64
#define WINDOW  256
#define LN_EPS  1e-5f

// ---------------- scratch (no allocations allowed) ----------------
__device__ float g_qkv[(size_t)S_LEN * 3 * DMODEL];   // [S, 3*D]  (q | k | v)
__device__ float g_attn[(size_t)S_LEN * DMODEL];      // attention output [S, D]
__device__ float g_res[(size_t)S_LEN * DMODEL];       // residual pre-LN [S, D]

// =====================================================================
// SGEMM: C[M,N] = A[M,K] @ B[K,N] (+ Cadd), row-major, 128x128x16 tile,
// 256 threads, 8x8 per-thread microtile.
// =====================================================================
__global__ void __launch_bounds__(256) sgemm_kernel(
    const float* __restrict__ A, const float* __restrict__ B,
    float* __restrict__ C, const float* __restrict__ Cadd,
    int M, int N, int K)
{
    __shared__ float As[16][128];
    __shared__ float Bs[16][128];

    const int tid = threadIdx.x;
    const int m0 = blockIdx.y * 128;
    const int n0 = blockIdx.x * 128;
    const int tx = tid & 15;
    const int ty = tid >> 4;

    float acc[8][8];
#pragma unroll
    for (int i = 0; i < 8; i++)
#pragma unroll
        for (int j = 0; j < 8; j++) acc[i][j] = 0.f;

    const int aRow = tid >> 2;          // 0..63 (and +64)
    const int aCol = (tid & 3) << 2;    // 0,4,8,12
    const int bRow = tid >> 5;          // 0..7 (and +8)
    const int bCol = (tid & 31) << 2;   // 0..124

    const float* Aptr = A + (size_t)(m0 + aRow) * K + aCol;
    const float* Bptr = B + (size_t)bRow * N + n0 + bCol;

    for (int k0 = 0; k0 < K; k0 += 16) {
        float4 a0 = *(const float4*)(Aptr + k0);
        float4 a1 = *(const float4*)(Aptr + (size_t)64 * K + k0);
        float4 b0 = *(const float4*)(Bptr + (size_t)k0 * N);
        float4 b1 = *(const float4*)(Bptr + (size_t)(k0 + 8) * N);

        __syncthreads();
        As[aCol + 0][aRow] = a0.x;
        As[aCol + 1][aRow] = a0.y;
        As[aCol + 2][aRow] = a0.z;
        As[aCol + 3][aRow] = a0.w;
        As[aCol + 0][aRow + 64] = a1.x;
        As[aCol + 1][aRow + 64] = a1.y;
        As[aCol + 2][aRow + 64] = a1.z;
        As[aCol + 3][aRow + 64] = a1.w;
        *(float4*)&Bs[bRow][bCol]     = b0;
        *(float4*)&Bs[bRow + 8][bCol] = b1;
        __syncthreads();

#pragma unroll
        for (int k = 0; k < 16; k++) {
            float4 av0 = *(const float4*)&As[k][ty * 8];
            float4 av1 = *(const float4*)&As[k][ty * 8 + 4];
            float4 bv0 = *(const float4*)&Bs[k][tx * 8];
            float4 bv1 = *(const float4*)&Bs[k][tx * 8 + 4];
            float a[8] = {av0.x, av0.y, av0.z, av0.w, av1.x, av1.y, av1.z, av1.w};
            float b[8] = {bv0.x, bv0.y, bv0.z, bv0.w, bv1.x, bv1.y, bv1.z, bv1.w};
#pragma unroll
            for (int i = 0; i < 8; i++)
#pragma unroll
                for (int j = 0; j < 8; j++)
                    acc[i][j] = fmaf(a[i], b[j], acc[i][j]);
        }
    }

#pragma unroll
    for (int i = 0; i < 8; i++) {
        size_t row = (size_t)(m0 + ty * 8 + i);
        float* cp = C + row * N + n0 + tx * 8;
        if (Cadd) {
            const float* ap = Cadd + row * N + n0 + tx * 8;
            float4 x0 = *(const float4*)ap;
            float4 x1 = *(const float4*)(ap + 4);
            acc[i][0] += x0.x; acc[i][1] += x0.y; acc[i][2] += x0.z; acc[i][3] += x0.w;
            acc[i][4] += x1.x; acc[i][5] += x1.y; acc[i][6] += x1.z; acc[i][7] += x1.w;
        }
        float4 o0 = make_float4(acc[i][0], acc[i][1], acc[i][2], acc[i][3]);
        float4 o1 = make_float4(acc[i][4], acc[i][5], acc[i][6], acc[i][7]);
        *(float4*)cp = o0;
        *(float4*)(cp + 4) = o1;
    }
}

// =====================================================================
// RoPE in-place on q,k parts of g_qkv. grid=S, block=512 (16 heads x 32)
// =====================================================================
__global__ void __launch_bounds__(512) rope_kernel()
{
    const int s = blockIdx.x;
    const int h = threadIdx.x >> 5;
    const int j = threadIdx.x & 31;

    // inv_freq = 10000^(-j/32) = 2^(-j*log2(10000)/32)
    const float LOG2_1E4 = 13.28771237954945f;
    float inv = exp2f(-(float)j * (LOG2_1E4 / 32.0f));
    float ang = (float)s * inv;
    float sn, cs;
    sincosf(ang, &sn, &cs);   // accurate version (full range reduction)

    float* q = g_qkv + (size_t)s * 3072 + h * 64;
    float* k = q + 1024;

    float q0 = q[j], q1 = q[j + 32];
    q[j]      = q0 * cs - q1 * sn;
    q[j + 32] = q1 * cs + q0 * sn;

    float k0 = k[j], k1 = k[j + 32];
    k[j]      = k0 * cs - k1 * sn;
    k[j + 32] = k1 * cs + k0 * sn;
}

// =====================================================================
// Windowed causal flash attention.
// grid = (NHEADS, S/64), block = 256 (16x16), 4x4 microtile, online softmax.
// =====================================================================
#define APITCH 68

__global__ void __launch_bounds__(256) attn_kernel()
{
    extern __shared__ float sm[];
    float* QT = sm;                   // [64][APITCH]  Q^T: [d][q], pre-scaled by 1/8
    float* KT = sm + 64 * APITCH;     // [64][APITCH]  K^T: [d][k]
    float* Vs = sm + 2 * 64 * APITCH; // [64][APITCH]  V:   [k][d]
    float* PT = sm + 3 * 64 * APITCH; // [64][APITCH]  P^T: [k][q]

    const int h  = blockIdx.x;
    const int q0 = blockIdx.y * 64;
    const int tid = threadIdx.x;
    const int tx = tid & 15;
    const int ty = tid >> 4;

    // ---- load Q tile (transposed, scaled by 1/sqrt(64)) ----
    {
        const int r  = tid >> 2;
        const int c0 = (tid & 3) * 16;
        const float* src = g_qkv + (size_t)(q0 + r) * 3072 + h * 64 + c0;
#pragma unroll
        for (int i = 0; i < 16; i += 4) {
            float4 v = *(const float4*)(src + i);
            QT[(c0 + i + 0) * APITCH + r] = v.x * 0.125f;
            QT[(c0 + i + 1) * APITCH + r] = v.y * 0.125f;
            QT[(c0 + i + 2) * APITCH + r] = v.z * 0.125f;
            QT[(c0 + i + 3) * APITCH + r] = v.w * 0.125f;
        }
    }

    float m_[4], l_[4], O[4][4];
#pragma unroll
    for (int i = 0; i < 4; i++) {
        m_[i] = -1e30f;
        l_[i] = 0.f;
#pragma unroll
        for (int j = 0; j < 4; j++) O[i][j] = 0.f;
    }

    int kstart = q0 - WINDOW;
    if (kstart < 0) kstart = 0;

    for (int kc = kstart; kc <= q0; kc += 64) {
        __syncthreads();   // previous chunk's P@V done before overwriting KT/Vs
        // ---- load K chunk (transposed) and V chunk (natural) ----
        {
            const int r  = tid >> 2;
            const int c0 = (tid & 3) * 16;
            const float* ks = g_qkv + (size_t)(kc + r) * 3072 + 1024 + h * 64 + c0;
            const float* vs = g_qkv + (size_t)(kc + r) * 3072 + 2048 + h * 64 + c0;
#pragma unroll
            for (int i = 0; i < 16; i += 4) {
                float4 kv = *(const float4*)(ks + i);
                KT[(c0 + i + 0) * APITCH + r] = kv.x;
                KT[(c0 + i + 1) * APITCH + r] = kv.y;
                KT[(c0 + i + 2) * APITCH + r] = kv.z;
                KT[(c0 + i + 3) * APITCH + r] = kv.w;
                float4 vv = *(const float4*)(vs + i);
                *(float4*)(Vs + (size_t)r * APITCH + c0 + i) = vv;
            }
        }
        __syncthreads();

        // ---- S = Q @ K^T (4x4 per thread) ----
        float acc[4][4];
#pragma unroll
        for (int i = 0; i < 4; i++)
#pragma unroll
            for (int j = 0; j < 4; j++) acc[i][j] = 0.f;

#pragma unroll 8
        for (int d = 0; d < 64; d++) {
            float4 a = *(const float4*)(QT + d * APITCH + ty * 4);
            float4 b = *(const float4*)(KT + d * APITCH + tx * 4);
            float av[4] = {a.x, a.y, a.z, a.w};
            float bv[4] = {b.x, b.y, b.z, b.w};
#pragma unroll
            for (int i = 0; i < 4; i++)
#pragma unroll
                for (int j = 0; j < 4; j++)
                    acc[i][j] = fmaf(av[i], bv[j], acc[i][j]);
        }

        // ---- mask + online softmax ----
#pragma unroll
        for (int i = 0; i < 4; i++) {
            const int q = q0 + ty * 4 + i;
            float rmax = -1e30f;
#pragma unroll
            for (int j = 0; j < 4; j++) {
                const int key = kc + tx * 4 + j;
                const bool ok = (key <= q) && (q - key <= WINDOW);
                if (!ok) acc[i][j] = -1e30f;
                rmax = fmaxf(rmax, acc[i][j]);
            }
#pragma unroll
            for (int o = 8; o >= 1; o >>= 1)
                rmax = fmaxf(rmax, __shfl_xor_sync(0xffffffffu, rmax, o));
            const float mnew = fmaxf(m_[i], rmax);
            const float scale = __expf(m_[i] - mnew);
            float rsum = 0.f;
#pragma unroll
            for (int j = 0; j < 4; j++) {
                const float p = __expf(acc[i][j] - mnew);
                PT[(size_t)(tx * 4 + j) * APITCH + ty * 4 + i] = p;
                rsum += p;
            }
#pragma unroll
            for (int o = 8; o >= 1; o >>= 1)
                rsum += __shfl_xor_sync(0xffffffffu, rsum, o);
            l_[i] = l_[i] * scale + rsum;
            m_[i] = mnew;
#pragma unroll
            for (int j = 0; j < 4; j++) O[i][j] *= scale;
        }
        __syncthreads();   // PT visible to all

        // ---- O += P @ V ----
#pragma unroll 8
        for (int k = 0; k < 64; k++) {
            float4 p = *(const float4*)(PT + (size_t)k * APITCH + ty * 4);
            float4 v = *(const float4*)(Vs + (size_t)k * APITCH + tx * 4);
            float pv[4] = {p.x, p.y, p.z, p.w};
            float vv[4] = {v.x, v.y, v.z, v.w};
#pragma unroll
            for (int i = 0; i < 4; i++)
#pragma unroll
                for (int j = 0; j < 4; j++)
                    O[i][j] = fmaf(pv[i], vv[j], O[i][j]);
        }
    }

    // ---- normalize + write [S, H*64] ----
#pragma unroll
    for (int i = 0; i < 4; i++) {
        const int s = q0 + ty * 4 + i;
        const float inv = 1.f / l_[i];
        float4 o = make_float4(O[i][0] * inv, O[i][1] * inv, O[i][2] * inv, O[i][3] * inv);
        *(float4*)(g_attn + (size_t)s * DMODEL + h * 64 + tx * 4) = o;
    }
}

// =====================================================================
// LayerNorm: grid=S, block=256 (4 floats per thread)
// =====================================================================
__global__ void __launch_bounds__(256) ln_kernel(
    const float* __restrict__ gamma, const float* __restrict__ beta,
    float* __restrict__ y)
{
    const int s = blockIdx.x;
    const int tid = threadIdx.x;
    const float* r = g_res + (size_t)s * DMODEL;

    float4 xv = *(const float4*)(r + tid * 4);
    float s1 = xv.x + xv.y + xv.z + xv.w;
    float s2 = xv.x * xv.x + xv.y * xv.y + xv.z * xv.z + xv.w * xv.w;
#pragma unroll
    for (int o = 16; o >= 1; o >>= 1) {
        s1 += __shfl_xor_sync(0xffffffffu, s1, o);
        s2 += __shfl_xor_sync(0xffffffffu, s2, o);
    }
    __shared__ float a1[8], a2[8];
    const int w = tid >> 5, lane = tid & 31;
    if (lane == 0) { a1[w] = s1; a2[w] = s2; }
    __syncthreads();
    float t1 = 0.f, t2 = 0.f;
#pragma unroll
    for (int i = 0; i < 8; i++) { t1 += a1[i]; t2 += a2[i]; }

    const float mu  = t1 * (1.0f / DMODEL);
    const float var = t2 * (1.0f / DMODEL) - mu * mu;
    const float rstd = rsqrtf(var + LN_EPS);

    const int c = tid * 4;
    float4 g = *(const float4*)(gamma + c);
    float4 b = *(const float4*)(beta + c);
    float4 o;
    o.x = (xv.x - mu) * rstd * g.x + b.x;
    o.y = (xv.y - mu) * rstd * g.y + b.y;
    o.z = (xv.z - mu) * rstd * g.z + b.z;
    o.w = (xv.w - mu) * rstd * g.w + b.w;
    *(float4*)(y + (size_t)s * DMODEL + c) = o;
}

// =====================================================================
// launch
// =====================================================================
extern "C" void kernel_launch(void* const* d_in, const int* in_sizes, int n_in,
                              void* d_out, int out_size)
{
    const float* x     = (const float*)d_in[0];
    const float* state = (const float*)d_in[1];
    const float* Wqkv  = (const float*)d_in[2];
    const float* Wout  = (const float*)d_in[3];
    const float* gamma = (const float*)d_in[4];
    const float* beta  = (const float*)d_in[5];
    float* y = (float*)d_out;

    float *qkv, *attn, *res;
    cudaGetSymbolAddress((void**)&qkv,  g_qkv);
    cudaGetSymbolAddress((void**)&attn, g_attn);
    cudaGetSymbolAddress((void**)&res,  g_res);

    // 1) QKV projection: [2048,1024] @ [1024,3072]
    sgemm_kernel<<<dim3(3 * DMODEL / 128, S_LEN / 128), 256>>>(
        x, Wqkv, qkv, nullptr, S_LEN, 3 * DMODEL, DMODEL);

    // 2) RoPE in place on q,k
    rope_kernel<<<S_LEN, 512>>>();

    // 3) windowed attention
    const int smem_bytes = 4 * 64 * APITCH * (int)sizeof(float);
    cudaFuncSetAttribute(attn_kernel, cudaFuncAttributeMaxDynamicSharedMemorySize, smem_bytes);
    attn_kernel<<<dim3(NHEADS, S_LEN / 64), 256, smem_bytes>>>();

    // 4) output projection + residual: res = x + attn @ W_out
    sgemm_kernel<<<dim3(DMODEL / 128, S_LEN / 128), 256>>>(
        attn, Wout, res, x, S_LEN, DMODEL, DMODEL);

    // 5) LayerNorm -> y
    ln_kernel<<<S_LEN, 256>>>(gamma, beta, y);

    // 6) pass-through state if the output buffer includes it
    if (out_size >= S_LEN * DMODEL + DMODEL) {
        cudaMemcpyAsync(y + (size_t)S_LEN * DMODEL, state,
                        DMODEL * sizeof(float), cudaMemcpyDeviceToDevice);
    }
}

// round 2
// speedup vs baseline: 1.0027x; 1.0027x over previous
#include <cuda_runtime.h>
#include <math.h>

#define S_LEN   2048
#define DMODEL  1024
#define NHEADS  16
#define HDIM    64
#define WINDOW  256
#define LN_EPS  1e-5f

// ---------------- scratch (no allocations allowed) ----------------
__device__ float g_qkv[(size_t)S_LEN * 3 * DMODEL];   // [S, 3*D]  (q | k | v)
__device__ float g_attn[(size_t)S_LEN * DMODEL];      // attention output [S, D]
__device__ float g_res[(size_t)S_LEN * DMODEL];       // residual pre-LN [S, D]

// =====================================================================
// SGEMM: C[M,N] = A[M,K] @ B[K,N] (+ Cadd), row-major, 128x128x16 tile,
// 256 threads, 8x8 per-thread microtile.
// =====================================================================
__global__ void __launch_bounds__(256) sgemm_kernel(
    const float* __restrict__ A, const float* __restrict__ B,
    float* __restrict__ C, const float* __restrict__ Cadd,
    int M, int N, int K)
{
    __shared__ float As[16][128];
    __shared__ float Bs[16][128];

    const int tid = threadIdx.x;
    const int m0 = blockIdx.y * 128;
    const int n0 = blockIdx.x * 128;
    const int tx = tid & 15;
    const int ty = tid >> 4;

    float acc[8][8];
#pragma unroll
    for (int i = 0; i < 8; i++)
#pragma unroll
        for (int j = 0; j < 8; j++) acc[i][j] = 0.f;

    const int aRow = tid >> 2;          // 0..63 (and +64)
    const int aCol = (tid & 3) << 2;    // 0,4,8,12
    const int bRow = tid >> 5;          // 0..7 (and +8)
    const int bCol = (tid & 31) << 2;   // 0..124

    const float* Aptr = A + (size_t)(m0 + aRow) * K + aCol;
    const float* Bptr = B + (size_t)bRow * N + n0 + bCol;

    for (int k0 = 0; k0 < K; k0 += 16) {
        float4 a0 = *(const float4*)(Aptr + k0);
        float4 a1 = *(const float4*)(Aptr + (size_t)64 * K + k0);
        float4 b0 = *(const float4*)(Bptr + (size_t)k0 * N);
        float4 b1 = *(const float4*)(Bptr + (size_t)(k0 + 8) * N);

        __syncthreads();
        As[aCol + 0][aRow] = a0.x;
        As[aCol + 1][aRow] = a0.y;
        As[aCol + 2][aRow] = a0.z;
        As[aCol + 3][aRow] = a0.w;
        As[aCol + 0][aRow + 64] = a1.x;
        As[aCol + 1][aRow + 64] = a1.y;
        As[aCol + 2][aRow + 64] = a1.z;
        As[aCol + 3][aRow + 64] = a1.w;
        *(float4*)&Bs[bRow][bCol]     = b0;
        *(float4*)&Bs[bRow + 8][bCol] = b1;
        __syncthreads();

#pragma unroll
        for (int k = 0; k < 16; k++) {
            float4 av0 = *(const float4*)&As[k][ty * 8];
            float4 av1 = *(const float4*)&As[k][ty * 8 + 4];
            float4 bv0 = *(const float4*)&Bs[k][tx * 8];
            float4 bv1 = *(const float4*)&Bs[k][tx * 8 + 4];
            float a[8] = {av0.x, av0.y, av0.z, av0.w, av1.x, av1.y, av1.z, av1.w};
            float b[8] = {bv0.x, bv0.y, bv0.z, bv0.w, bv1.x, bv1.y, bv1.z, bv1.w};
#pragma unroll
            for (int i = 0; i < 8; i++)
#pragma unroll
                for (int j = 0; j < 8; j++)
                    acc[i][j] = fmaf(a[i], b[j], acc[i][j]);
        }
    }

#pragma unroll
    for (int i = 0; i < 8; i++) {
        size_t row = (size_t)(m0 + ty * 8 + i);
        float* cp = C + row * N + n0 + tx * 8;
        if (Cadd) {
            const float* ap = Cadd + row * N + n0 + tx * 8;
            float4 x0 = *(const float4*)ap;
            float4 x1 = *(const float4*)(ap + 4);
            acc[i][0] += x0.x; acc[i][1] += x0.y; acc[i][2] += x0.z; acc[i][3] += x0.w;
            acc[i][4] += x1.x; acc[i][5] += x1.y; acc[i][6] += x1.z; acc[i][7] += x1.w;
        }
        float4 o0 = make_float4(acc[i][0], acc[i][1], acc[i][2], acc[i][3]);
        float4 o1 = make_float4(acc[i][4], acc[i][5], acc[i][6], acc[i][7]);
        *(float4*)cp = o0;
        *(float4*)(cp + 4) = o1;
    }
}

// =====================================================================
// RoPE in-place on q,k parts of g_qkv. grid=S, block=512 (16 heads x 32)
// =====================================================================
__global__ void __launch_bounds__(512) rope_kernel()
{
    const int s = blockIdx.x;
    const int h = threadIdx.x >> 5;
    const int j = threadIdx.x & 31;

    // inv_freq = 10000^(-j/32) = 2^(-j*log2(10000)/32)
    const float LOG2_1E4 = 13.28771237954945f;
    float inv = exp2f(-(float)j * (LOG2_1E4 / 32.0f));
    float ang = (float)s * inv;
    float sn, cs;
    sincosf(ang, &sn, &cs);   // accurate version (full range reduction)

    float* q = g_qkv + (size_t)s * 3072 + h * 64;
    float* k = q + 1024;

    float q0 = q[j], q1 = q[j + 32];
    q[j]      = q0 * cs - q1 * sn;
    q[j + 32] = q1 * cs + q0 * sn;

    float k0 = k[j], k1 = k[j + 32];
    k[j]      = k0 * cs - k1 * sn;
    k[j + 32] = k1 * cs + k0 * sn;
}

// =====================================================================
// Windowed causal flash attention.
// grid = (NHEADS, S/64), block = 256 (16x16), 4x4 microtile, online softmax.
// =====================================================================
#define APITCH 68

__global__ void __launch_bounds__(256) attn_kernel()
{
    extern __shared__ float sm[];
    float* QT = sm;                   // [64][APITCH]  Q^T: [d][q], pre-scaled by 1/8
    float* KT = sm + 64 * APITCH;     // [64][APITCH]  K^T: [d][k]
    float* Vs = sm + 2 * 64 * APITCH; // [64][APITCH]  V:   [k][d]
    float* PT = sm + 3 * 64 * APITCH; // [64][APITCH]  P^T: [k][q]

    const int h  = blockIdx.x;
    const int q0 = blockIdx.y * 64;
    const int tid = threadIdx.x;
    const int tx = tid & 15;
    const int ty = tid >> 4;

    // ---- load Q tile (transposed, scaled by 1/sqrt(64)) ----
    {
        const int r  = tid >> 2;
        const int c0 = (tid & 3) * 16;
        const float* src = g_qkv + (size_t)(q0 + r) * 3072 + h * 64 + c0;
#pragma unroll
        for (int i = 0; i < 16; i += 4) {
            float4 v = *(const float4*)(src + i);
            QT[(c0 + i + 0) * APITCH + r] = v.x * 0.125f;
            QT[(c0 + i + 1) * APITCH + r] = v.y * 0.125f;
            QT[(c0 + i + 2) * APITCH + r] = v.z * 0.125f;
            QT[(c0 + i + 3) * APITCH + r] = v.w * 0.125f;
        }
    }

    float m_[4], l_[4], O[4][4];
#pragma unroll
    for (int i = 0; i < 4; i++) {
        m_[i] = -1e30f;
        l_[i] = 0.f;
#pragma unroll
        for (int j = 0; j < 4; j++) O[i][j] = 0.f;
    }

    int kstart = q0 - WINDOW;
    if (kstart < 0) kstart = 0;

    for (int kc = kstart; kc <= q0; kc += 64) {
        __syncthreads();   // previous chunk's P@V done before overwriting KT/Vs
        // ---- load K chunk (transposed) and V chunk (natural) ----
        {
            const int r  = tid >> 2;
            const int c0 = (tid & 3) * 16;
            const float* ks = g_qkv + (size_t)(kc + r) * 3072 + 1024 + h * 64 + c0;
            const float* vs = g_qkv + (size_t)(kc + r) * 3072 + 2048 + h * 64 + c0;
#pragma unroll
            for (int i = 0; i < 16; i += 4) {
                float4 kv = *(const float4*)(ks + i);
                KT[(c0 + i + 0) * APITCH + r] = kv.x;
                KT[(c0 + i + 1) * APITCH + r] = kv.y;
                KT[(c0 + i + 2) * APITCH + r] = kv.z;
                KT[(c0 + i + 3) * APITCH + r] = kv.w;
                float4 vv = *(const float4*)(vs + i);
                *(float4*)(Vs + (size_t)r * APITCH + c0 + i) = vv;
            }
        }
        __syncthreads();

        // ---- S = Q @ K^T (4x4 per thread) ----
        float acc[4][4];
#pragma unroll
        for (int i = 0; i < 4; i++)
#pragma unroll
            for (int j = 0; j < 4; j++) acc[i][j] = 0.f;

#pragma unroll 8
        for (int d = 0; d < 64; d++) {
            float4 a = *(const float4*)(QT + d * APITCH + ty * 4);
            float4 b = *(const float4*)(KT + d * APITCH + tx * 4);
            float av[4] = {a.x, a.y, a.z, a.w};
            float bv[4] = {b.x, b.y, b.z, b.w};
#pragma unroll
            for (int i = 0; i < 4; i++)
#pragma unroll
                for (int j = 0; j < 4; j++)
                    acc[i][j] = fmaf(av[i], bv[j], acc[i][j]);
        }

        // ---- mask + online softmax ----
#pragma unroll
        for (int i = 0; i < 4; i++) {
            const int q = q0 + ty * 4 + i;
            float rmax = -1e30f;
#pragma unroll
            for (int j = 0; j < 4; j++) {
                const int key = kc + tx * 4 + j;
                const bool ok = (key <= q) && (q - key <= WINDOW);
                if (!ok) acc[i][j] = -1e30f;
                rmax = fmaxf(rmax, acc[i][j]);
            }
#pragma unroll
            for (int o = 8; o >= 1; o >>= 1)
                rmax = fmaxf(rmax, __shfl_xor_sync(0xffffffffu, rmax, o));
            const float mnew = fmaxf(m_[i], rmax);
            const float scale = __expf(m_[i] - mnew);
            float rsum = 0.f;
#pragma unroll
            for (int j = 0; j < 4; j++) {
                const float p = __expf(acc[i][j] - mnew);
                PT[(size_t)(tx * 4 + j) * APITCH + ty * 4 + i] = p;
                rsum += p;
            }
#pragma unroll
            for (int o = 8; o >= 1; o >>= 1)
                rsum += __shfl_xor_sync(0xffffffffu, rsum, o);
            l_[i] = l_[i] * scale + rsum;
            m_[i] = mnew;
#pragma unroll
            for (int j = 0; j < 4; j++) O[i][j] *= scale;
        }
        __syncthreads();   // PT visible to all

        // ---- O += P @ V ----
#pragma unroll 8
        for (int k = 0; k < 64; k++) {
            float4 p = *(const float4*)(PT + (size_t)k * APITCH + ty * 4);
            float4 v = *(const float4*)(Vs + (size_t)k * APITCH + tx * 4);
            float pv[4] = {p.x, p.y, p.z, p.w};
            float vv[4] = {v.x, v.y, v.z, v.w};
#pragma unroll
            for (int i = 0; i < 4; i++)
#pragma unroll
                for (int j = 0; j < 4; j++)
                    O[i][j] = fmaf(pv[i], vv[j], O[i][j]);
        }
    }

    // ---- normalize + write [S, H*64] ----
#pragma unroll
    for (int i = 0; i < 4; i++) {
        const int s = q0 + ty * 4 + i;
        const float inv = 1.f / l_[i];
        float4 o = make_float4(O[i][0] * inv, O[i][1] * inv, O[i][2] * inv, O[i][3] * inv);
        *(float4*)(g_attn + (size_t)s * DMODEL + h * 64 + tx * 4) = o;
    }
}

// =====================================================================
// LayerNorm: grid=S, block=256 (4 floats per thread)
// =====================================================================
__global__ void __launch_bounds__(256) ln_kernel(
    const float* __restrict__ gamma, const float* __restrict__ beta,
    float* __restrict__ y)
{
    const int s = blockIdx.x;
    const int tid = threadIdx.x;
    const float* r = g_res + (size_t)s * DMODEL;

    float4 xv = *(const float4*)(r + tid * 4);
    float s1 = xv.x + xv.y + xv.z + xv.w;
    float s2 = xv.x * xv.x + xv.y * xv.y + xv.z * xv.z + xv.w * xv.w;
#pragma unroll
    for (int o = 16; o >= 1; o >>= 1) {
        s1 += __shfl_xor_sync(0xffffffffu, s1, o);
        s2 += __shfl_xor_sync(0xffffffffu, s2, o);
    }
    __shared__ float a1[8], a2[8];
    const int w = tid >> 5, lane = tid & 31;
    if (lane == 0) { a1[w] = s1; a2[w] = s2; }
    __syncthreads();
    float t1 = 0.f, t2 = 0.f;
#pragma unroll
    for (int i = 0; i < 8; i++) { t1 += a1[i]; t2 += a2[i]; }

    const float mu  = t1 * (1.0f / DMODEL);
    const float var = t2 * (1.0f / DMODEL) - mu * mu;
    const float rstd = rsqrtf(var + LN_EPS);

    const int c = tid * 4;
    float4 g = *(const float4*)(gamma + c);
    float4 b = *(const float4*)(beta + c);
    float4 o;
    o.x = (xv.x - mu) * rstd * g.x + b.x;
    o.y = (xv.y - mu) * rstd * g.y + b.y;
    o.z = (xv.z - mu) * rstd * g.z + b.z;
    o.w = (xv.w - mu) * rstd * g.w + b.w;
    *(float4*)(y + (size_t)s * DMODEL + c) = o;
}

// =====================================================================
// launch
// =====================================================================
extern "C" void kernel_launch(void* const* d_in, const int* in_sizes, int n_in,
                              void* d_out, int out_size)
{
    const float* x     = (const float*)d_in[0];
    const float* state = (const float*)d_in[1];
    const float* Wqkv  = (const float*)d_in[2];
    const float* Wout  = (const float*)d_in[3];
    const float* gamma = (const float*)d_in[4];
    const float* beta  = (const float*)d_in[5];
    float* y = (float*)d_out;

    float *qkv, *attn, *res;
    cudaGetSymbolAddress((void**)&qkv,  g_qkv);
    cudaGetSymbolAddress((void**)&attn, g_attn);
    cudaGetSymbolAddress((void**)&res,  g_res);

    // 1) QKV projection: [2048,1024] @ [1024,3072]
    sgemm_kernel<<<dim3(3 * DMODEL / 128, S_LEN / 128), 256>>>(
        x, Wqkv, qkv, nullptr, S_LEN, 3 * DMODEL, DMODEL);

    // 2) RoPE in place on q,k
    rope_kernel<<<S_LEN, 512>>>();

    // 3) windowed attention
    const int smem_bytes = 4 * 64 * APITCH * (int)sizeof(float);
    cudaFuncSetAttribute(attn_kernel, cudaFuncAttributeMaxDynamicSharedMemorySize, smem_bytes);
    attn_kernel<<<dim3(NHEADS, S_LEN / 64), 256, smem_bytes>>>();

    // 4) output projection + residual: res = x + attn @ W_out
    sgemm_kernel<<<dim3(DMODEL / 128, S_LEN / 128), 256>>>(
        attn, Wout, res, x, S_LEN, DMODEL, DMODEL);

    // 5) LayerNorm -> y
    ln_kernel<<<S_LEN, 256>>>(gamma, beta, y);

    // 6) pass-through state if the output buffer includes it
    if (out_size >= S_LEN * DMODEL + DMODEL) {
        cudaMemcpyAsync(y + (size_t)S_LEN * DMODEL, state,
                        DMODEL * sizeof(float), cudaMemcpyDeviceToDevice);
    }
}